// round 16
// baseline (speedup 1.0000x reference)
#include <cuda_runtime.h>

// Problem constants (fixed by the reference):
//   obj_coord [B,Q,4] f32, sub_coord [B,Q,4] f32, img_size [B,2] int32 (JAX x64 off),
//   mask [B,H,W] bool (shape only, ignored)
//   output [2,B,Q,H,W] f32, value 1.0 OUTSIDE the (inclusive) box, 0.0 inside.
#define BB 64
#define QQ 300
#define HM 40
#define WM 40

// One block per output plane (s,b,q). 128 threads write 400 float4 = 1600 floats.
__global__ __launch_bounds__(128) void part_mask_kernel(
    const float* __restrict__ obj_coord,
    const float* __restrict__ sub_coord,
    const int* __restrict__ img_size,
    float* __restrict__ out)
{
    const int plane = blockIdx.x;          // plane = s*B*Q + b*Q + q  (matches output layout)
    const int q  = plane % QQ;
    const int sb = plane / QQ;
    const int b  = sb % BB;
    const int s  = sb / BB;                // 0 = object, 1 = human(sub)

    const float* coord = (s == 0 ? obj_coord : sub_coord) + (size_t)(b * QQ + q) * 4;
    const float4 c = *reinterpret_cast<const float4*>(coord);   // cx, cy, w, h

    const float sh = (float)img_size[2 * b + 0];   // img_h
    const float sw = (float)img_size[2 * b + 1];   // img_w

    // Match JAX's unfused f32 evaluation exactly:
    //   x1 = floor( (cx - 0.5*w) * sw / 32 )   [/32 == *0.03125 exactly]
    const float hw = __fmul_rn(0.5f, c.z);
    const float hh = __fmul_rn(0.5f, c.w);
    const float x1f = __fmul_rn(__fmul_rn(__fsub_rn(c.x, hw), sw), 0.03125f);
    const float y1f = __fmul_rn(__fmul_rn(__fsub_rn(c.y, hh), sh), 0.03125f);
    const float x2f = __fmul_rn(__fmul_rn(__fadd_rn(c.x, hw), sw), 0.03125f);
    const float y2f = __fmul_rn(__fmul_rn(__fadd_rn(c.y, hh), sh), 0.03125f);

    const int x1 = (int)floorf(x1f);
    const int y1 = (int)floorf(y1f);
    const int x2 = min((int)floorf(x2f), WM - 1);
    const int y2 = min((int)floorf(y2f), HM - 1);

    float4* po = reinterpret_cast<float4*>(out + (size_t)plane * (HM * WM));

    // 400 float4 per plane; 128 threads -> <=4 iterations, fully coalesced STG.128
    #pragma unroll 4
    for (int v = threadIdx.x; v < (HM * WM) / 4; v += 128) {
        const int h  = v / (WM / 4);
        const int wb = (v % (WM / 4)) * 4;
        const bool rout = (h < y1) | (h > y2);
        float4 r;
        r.x = (rout | (wb + 0 < x1) | (wb + 0 > x2)) ? 1.0f : 0.0f;
        r.y = (rout | (wb + 1 < x1) | (wb + 1 > x2)) ? 1.0f : 0.0f;
        r.z = (rout | (wb + 2 < x1) | (wb + 2 > x2)) ? 1.0f : 0.0f;
        r.w = (rout | (wb + 3 < x1) | (wb + 3 > x2)) ? 1.0f : 0.0f;
        po[v] = r;
    }
}

extern "C" void kernel_launch(void* const* d_in, const int* in_sizes, int n_in,
                              void* d_out, int out_size) {
    const float* obj = (const float*)d_in[0];
    const float* sub = (const float*)d_in[1];
    const int*   img = (const int*)d_in[2];
    // d_in[3] = mask: only its shape is used by the reference; ignored here.
    float* out = (float*)d_out;

    part_mask_kernel<<<2 * BB * QQ, 128>>>(obj, sub, img, out);
}